// round 5
// baseline (speedup 1.0000x reference)
#include <cuda_runtime.h>

#define N_NODES 4096
#define IN_DIM  512
#define H_HEADS 8
#define ATT_DIM 64
#define OUT_DIM 64
#define HD      512   // H * ATT_DIM == H * OUT_DIM

// Scratch (device globals: allocation-free per harness rules)
__device__ float g_q[N_NODES * HD];
__device__ float g_k[N_NODES * HD];
__device__ float g_v[N_NODES * HD];
__device__ float g_att[N_NODES * HD];

// ---------------------------------------------------------------------------
// Projection GEMM: C[4096,512] = (A[4096,512] @ W[512,512] + bias) * scale
// 128x128 tile, BK=8, 256 threads, 8x8 per thread.
// ---------------------------------------------------------------------------
__global__ __launch_bounds__(256) void proj_gemm(const float* __restrict__ A,
                                                 const float* __restrict__ W,
                                                 const float* __restrict__ bias,
                                                 float* __restrict__ C,
                                                 float scale) {
    __shared__ float As[8][132];
    __shared__ float Bs[8][132];
    const int tid = threadIdx.x;
    const int tx = tid & 15, ty = tid >> 4;
    const int bm = blockIdx.y * 128;
    const int bn = blockIdx.x * 128;

    float acc[8][8];
#pragma unroll
    for (int r = 0; r < 8; r++)
#pragma unroll
        for (int c = 0; c < 8; c++) acc[r][c] = 0.f;

    const int arow = tid >> 1;          // 0..127
    const int akk  = (tid & 1) * 4;     // 0 or 4
    const int bkk  = tid >> 5;          // 0..7
    const int bj   = (tid & 31) * 4;    // 0..124

    for (int k0 = 0; k0 < IN_DIM; k0 += 8) {
        float4 av = *(const float4*)&A[(bm + arow) * IN_DIM + k0 + akk];
        float4 bv = *(const float4*)&W[(k0 + bkk) * HD + bn + bj];
        __syncthreads();
        As[akk + 0][arow] = av.x;
        As[akk + 1][arow] = av.y;
        As[akk + 2][arow] = av.z;
        As[akk + 3][arow] = av.w;
        *(float4*)&Bs[bkk][bj] = bv;
        __syncthreads();
#pragma unroll
        for (int kk = 0; kk < 8; kk++) {
            float4 a0 = *(float4*)&As[kk][ty * 8];
            float4 a1 = *(float4*)&As[kk][ty * 8 + 4];
            float4 b0 = *(float4*)&Bs[kk][tx * 8];
            float4 b1 = *(float4*)&Bs[kk][tx * 8 + 4];
            float ar[8] = {a0.x, a0.y, a0.z, a0.w, a1.x, a1.y, a1.z, a1.w};
            float br[8] = {b0.x, b0.y, b0.z, b0.w, b1.x, b1.y, b1.z, b1.w};
#pragma unroll
            for (int r = 0; r < 8; r++)
#pragma unroll
                for (int c = 0; c < 8; c++) acc[r][c] += ar[r] * br[c];
        }
    }

    float bl[8];
#pragma unroll
    for (int c = 0; c < 8; c++) bl[c] = bias[bn + tx * 8 + c];
#pragma unroll
    for (int r = 0; r < 8; r++) {
        const int row = bm + ty * 8 + r;
        float4 o0, o1;
        o0.x = (acc[r][0] + bl[0]) * scale;
        o0.y = (acc[r][1] + bl[1]) * scale;
        o0.z = (acc[r][2] + bl[2]) * scale;
        o0.w = (acc[r][3] + bl[3]) * scale;
        o1.x = (acc[r][4] + bl[4]) * scale;
        o1.y = (acc[r][5] + bl[5]) * scale;
        o1.z = (acc[r][6] + bl[6]) * scale;
        o1.w = (acc[r][7] + bl[7]) * scale;
        *(float4*)&C[row * HD + bn + tx * 8]     = o0;
        *(float4*)&C[row * HD + bn + tx * 8 + 4] = o1;
    }
}

// ---------------------------------------------------------------------------
// Attention: one CTA = (64-query block, one head). One-pass streaming softmax
// (scores bounded in (-0.5, 0.6) => exp safe without running max).
// smem tiles pitch 68 (float4-aligned, conflict-free vector access).
// ---------------------------------------------------------------------------
#define PITCH 68
#define ATT_SMEM (5 * 64 * PITCH * 4)

__global__ __launch_bounds__(256) void attn_kernel(const float* __restrict__ adj) {
    extern __shared__ float sm[];
    float* q_s   = sm;                    // [d][i]  transposed
    float* k_s   = q_s   + 64 * PITCH;    // [d][j]  transposed
    float* v_s   = k_s   + 64 * PITCH;    // [j][e]
    float* adj_s = v_s   + 64 * PITCH;    // [i][j]
    float* p_s   = adj_s + 64 * PITCH;    // [j][i]  transposed

    const int tid = threadIdx.x;
    const int tx = tid & 15, ty = tid >> 4;
    const int tx4 = tx * 4, ty4 = ty * 4;
    const int qb = blockIdx.x;            // 0..63
    const int h  = blockIdx.y;            // 0..7
    const int hoff = h * ATT_DIM;

    // Load q tile transposed (once). q is pre-scaled by 1/sqrt(d).
    {
        const int i  = tid >> 2;
        const int dg = (tid & 3) * 16;
        const float* qrow = &g_q[(qb * 64 + i) * HD + hoff + dg];
#pragma unroll
        for (int c = 0; c < 4; c++) {
            float4 v4 = *(const float4*)(qrow + c * 4);
            q_s[(dg + c * 4 + 0) * PITCH + i] = v4.x;
            q_s[(dg + c * 4 + 1) * PITCH + i] = v4.y;
            q_s[(dg + c * 4 + 2) * PITCH + i] = v4.z;
            q_s[(dg + c * 4 + 3) * PITCH + i] = v4.w;
        }
    }

    float acc[4][4];
#pragma unroll
    for (int a = 0; a < 4; a++)
#pragma unroll
        for (int b = 0; b < 4; b++) acc[a][b] = 0.f;
    float rsum[4] = {0.f, 0.f, 0.f, 0.f};

    for (int kb = 0; kb < 64; kb++) {
        __syncthreads();  // previous iteration's PV reads done
        {
            const int j  = tid >> 2;
            const int dg = (tid & 3) * 16;
            const float* krow = &g_k[(kb * 64 + j) * HD + hoff + dg];
#pragma unroll
            for (int c = 0; c < 4; c++) {
                float4 v4 = *(const float4*)(krow + c * 4);
                k_s[(dg + c * 4 + 0) * PITCH + j] = v4.x;
                k_s[(dg + c * 4 + 1) * PITCH + j] = v4.y;
                k_s[(dg + c * 4 + 2) * PITCH + j] = v4.z;
                k_s[(dg + c * 4 + 3) * PITCH + j] = v4.w;
            }
            const float* vrow = &g_v[(kb * 64 + j) * HD + hoff + dg];
#pragma unroll
            for (int c = 0; c < 4; c++)
                *(float4*)&v_s[j * PITCH + dg + c * 4] = *(const float4*)(vrow + c * 4);
            const float* arow = &adj[(qb * 64 + j) * (size_t)N_NODES + kb * 64 + dg];
#pragma unroll
            for (int c = 0; c < 4; c++)
                *(float4*)&adj_s[j * PITCH + dg + c * 4] = *(const float4*)(arow + c * 4);
        }
        __syncthreads();

        // S = (q*scale) @ k^T  (4x4 per thread)
        float s[4][4];
#pragma unroll
        for (int a = 0; a < 4; a++)
#pragma unroll
            for (int b = 0; b < 4; b++) s[a][b] = 0.f;
#pragma unroll 8
        for (int d = 0; d < 64; d++) {
            float4 qa = *(float4*)(q_s + d * PITCH + ty4);
            float4 kv = *(float4*)(k_s + d * PITCH + tx4);
            float qr[4] = {qa.x, qa.y, qa.z, qa.w};
            float kr[4] = {kv.x, kv.y, kv.z, kv.w};
#pragma unroll
            for (int a = 0; a < 4; a++)
#pragma unroll
                for (int b = 0; b < 4; b++) s[a][b] += qr[a] * kr[b];
        }

        // P = exp(sigmoid(S) - 0.5 + 0.1*adj); accumulate row sums; stage P^T
#pragma unroll
        for (int a = 0; a < 4; a++) {
            float4 ad = *(float4*)&adj_s[(ty4 + a) * PITCH + tx4];
            float adv[4] = {ad.x, ad.y, ad.z, ad.w};
#pragma unroll
            for (int b = 0; b < 4; b++) {
                float x   = s[a][b];
                float sig = __fdividef(1.0f, 1.0f + __expf(-x));
                float p   = __expf(sig - 0.5f + 0.1f * adv[b]);
                rsum[a] += p;
                p_s[(tx4 + b) * PITCH + (ty4 + a)] = p;
            }
        }
        __syncthreads();

        // acc += P @ V
#pragma unroll 8
        for (int j = 0; j < 64; j++) {
            float4 pa = *(float4*)(p_s + j * PITCH + ty4);
            float4 vv = *(float4*)(v_s + j * PITCH + tx4);
            float pr[4] = {pa.x, pa.y, pa.z, pa.w};
            float vr[4] = {vv.x, vv.y, vv.z, vv.w};
#pragma unroll
            for (int a = 0; a < 4; a++)
#pragma unroll
                for (int b = 0; b < 4; b++) acc[a][b] += pr[a] * vr[b];
        }
    }

    // Row-sum reduce across the 16 tx-threads (same warp half), then normalize.
    float inv[4];
#pragma unroll
    for (int a = 0; a < 4; a++) {
        float s = rsum[a];
        s += __shfl_xor_sync(0xffffffffu, s, 8);
        s += __shfl_xor_sync(0xffffffffu, s, 4);
        s += __shfl_xor_sync(0xffffffffu, s, 2);
        s += __shfl_xor_sync(0xffffffffu, s, 1);
        inv[a] = __fdividef(1.0f, s);
    }

#pragma unroll
    for (int a = 0; a < 4; a++) {
        const int row = qb * 64 + ty4 + a;
        float4 o;
        o.x = acc[a][0] * inv[a];
        o.y = acc[a][1] * inv[a];
        o.z = acc[a][2] * inv[a];
        o.w = acc[a][3] * inv[a];
        *(float4*)&g_att[row * HD + hoff + tx4] = o;
    }
}

// ---------------------------------------------------------------------------
// Output projection: out[4096,64] = g_att[4096,512] @ WO[512,64] + bO
// 64x64 tile per CTA, BK=32, 256 threads, 4x4 per thread.
// ---------------------------------------------------------------------------
__global__ __launch_bounds__(256) void out_gemm(const float* __restrict__ WO,
                                                const float* __restrict__ bO,
                                                float* __restrict__ out) {
    __shared__ float As[32][68];
    __shared__ float Bs[32][68];
    const int tid = threadIdx.x;
    const int tx = tid & 15, ty = tid >> 4;
    const int bm = blockIdx.x * 64;

    float acc[4][4];
#pragma unroll
    for (int a = 0; a < 4; a++)
#pragma unroll
        for (int b = 0; b < 4; b++) acc[a][b] = 0.f;

    const int ar  = tid >> 2;          // 0..63
    const int akg = (tid & 3) * 8;     // 0,8,16,24
    const int bk  = tid >> 3;          // 0..31
    const int bjg = (tid & 7) * 8;     // 0..56

    for (int k0 = 0; k0 < HD; k0 += 32) {
        __syncthreads();
#pragma unroll
        for (int c = 0; c < 2; c++) {
            float4 v4 = *(const float4*)&g_att[(bm + ar) * HD + k0 + akg + c * 4];
            As[akg + c * 4 + 0][ar] = v4.x;
            As[akg + c * 4 + 1][ar] = v4.y;
            As[akg + c * 4 + 2][ar] = v4.z;
            As[akg + c * 4 + 3][ar] = v4.w;
        }
#pragma unroll
        for (int c = 0; c < 2; c++)
            *(float4*)&Bs[bk][bjg + c * 4] =
                *(const float4*)&WO[(k0 + bk) * OUT_DIM + bjg + c * 4];
        __syncthreads();
#pragma unroll
        for (int kk = 0; kk < 32; kk++) {
            float4 a4 = *(float4*)&As[kk][ty * 4];
            float4 b4 = *(float4*)&Bs[kk][tx * 4];
            float arr[4] = {a4.x, a4.y, a4.z, a4.w};
            float brr[4] = {b4.x, b4.y, b4.z, b4.w};
#pragma unroll
            for (int a = 0; a < 4; a++)
#pragma unroll
                for (int b = 0; b < 4; b++) acc[a][b] += arr[a] * brr[b];
        }
    }

    float bl[4];
#pragma unroll
    for (int b = 0; b < 4; b++) bl[b] = bO[tx * 4 + b];
#pragma unroll
    for (int a = 0; a < 4; a++) {
        float4 o;
        o.x = acc[a][0] + bl[0];
        o.y = acc[a][1] + bl[1];
        o.z = acc[a][2] + bl[2];
        o.w = acc[a][3] + bl[3];
        *(float4*)&out[(bm + ty * 4 + a) * OUT_DIM + tx * 4] = o;
    }
}

// ---------------------------------------------------------------------------
extern "C" void kernel_launch(void* const* d_in, const int* in_sizes, int n_in,
                              void* d_out, int out_size) {
    const float* Q   = (const float*)d_in[0];
    const float* K   = (const float*)d_in[1];
    const float* V   = (const float*)d_in[2];
    const float* adj = (const float*)d_in[3];
    const float* WQ  = (const float*)d_in[4];
    const float* bQ  = (const float*)d_in[5];
    const float* WK  = (const float*)d_in[6];
    const float* bK  = (const float*)d_in[7];
    const float* WV  = (const float*)d_in[8];
    const float* bV  = (const float*)d_in[9];
    const float* WO  = (const float*)d_in[10];
    const float* bO  = (const float*)d_in[11];
    float* out = (float*)d_out;

    float *qp, *kp, *vp;
    cudaGetSymbolAddress((void**)&qp, g_q);
    cudaGetSymbolAddress((void**)&kp, g_k);
    cudaGetSymbolAddress((void**)&vp, g_v);

    dim3 pgrid(HD / 128, N_NODES / 128);  // (4, 32)
    proj_gemm<<<pgrid, 256>>>(Q, WQ, bQ, qp, 0.125f);  // q pre-scaled by d^-0.5
    proj_gemm<<<pgrid, 256>>>(K, WK, bK, kp, 1.0f);
    proj_gemm<<<pgrid, 256>>>(V, WV, bV, vp, 1.0f);

    cudaFuncSetAttribute(attn_kernel,
                         cudaFuncAttributeMaxDynamicSharedMemorySize, ATT_SMEM);
    attn_kernel<<<dim3(64, 8), 256, ATT_SMEM>>>(adj);

    out_gemm<<<N_NODES / 64, 256>>>(WO, bO, out);
}

// round 6
// speedup vs baseline: 2.2521x; 2.2521x over previous
#include <cuda_runtime.h>

#define N_NODES 4096
#define IN_DIM  512
#define HD      512   // H * ATT_DIM
#define ATT_DIM 64

// Scratch (device globals: allocation-free per harness rules)
__device__ float g_q[N_NODES * HD];
__device__ float g_k[N_NODES * HD];
__device__ float g_v[N_NODES * HD];
__device__ float g_att[N_NODES * HD];

// ---------------------------------------------------------------------------
// tf32 helpers
// ---------------------------------------------------------------------------
__device__ __forceinline__ unsigned f2tf(float f) {
    unsigned u;
    asm("cvt.rna.tf32.f32 %0, %1;" : "=r"(u) : "f"(f));
    return u;
}

__device__ __forceinline__ void mma_tf32(float c[4],
                                         const unsigned a[4],
                                         unsigned b0, unsigned b1) {
    asm volatile(
        "mma.sync.aligned.m16n8k8.row.col.f32.tf32.tf32.f32 "
        "{%0,%1,%2,%3}, {%4,%5,%6,%7}, {%8,%9}, {%0,%1,%2,%3};"
        : "+f"(c[0]), "+f"(c[1]), "+f"(c[2]), "+f"(c[3])
        : "r"(a[0]), "r"(a[1]), "r"(a[2]), "r"(a[3]), "r"(b0), "r"(b1));
}

// ---------------------------------------------------------------------------
// Projection GEMM: C = (A[4096,512] @ W[512,512] + bias) * scale, tf32-rounded
// 128x128 tile, BK=8, 256 threads, 8x8 per thread.
// ---------------------------------------------------------------------------
__global__ __launch_bounds__(256) void proj_gemm(const float* __restrict__ A,
                                                 const float* __restrict__ W,
                                                 const float* __restrict__ bias,
                                                 float* __restrict__ C,
                                                 float scale) {
    __shared__ float As[8][132];
    __shared__ float Bs[8][132];
    const int tid = threadIdx.x;
    const int tx = tid & 15, ty = tid >> 4;
    const int bm = blockIdx.y * 128;
    const int bn = blockIdx.x * 128;

    float acc[8][8];
#pragma unroll
    for (int r = 0; r < 8; r++)
#pragma unroll
        for (int c = 0; c < 8; c++) acc[r][c] = 0.f;

    const int arow = tid >> 1;
    const int akk  = (tid & 1) * 4;
    const int bkk  = tid >> 5;
    const int bj   = (tid & 31) * 4;

    for (int k0 = 0; k0 < IN_DIM; k0 += 8) {
        float4 av = *(const float4*)&A[(bm + arow) * IN_DIM + k0 + akk];
        float4 bv = *(const float4*)&W[(k0 + bkk) * HD + bn + bj];
        __syncthreads();
        As[akk + 0][arow] = av.x;
        As[akk + 1][arow] = av.y;
        As[akk + 2][arow] = av.z;
        As[akk + 3][arow] = av.w;
        *(float4*)&Bs[bkk][bj] = bv;
        __syncthreads();
#pragma unroll
        for (int kk = 0; kk < 8; kk++) {
            float4 a0 = *(float4*)&As[kk][ty * 8];
            float4 a1 = *(float4*)&As[kk][ty * 8 + 4];
            float4 b0 = *(float4*)&Bs[kk][tx * 8];
            float4 b1 = *(float4*)&Bs[kk][tx * 8 + 4];
            float ar[8] = {a0.x, a0.y, a0.z, a0.w, a1.x, a1.y, a1.z, a1.w};
            float br[8] = {b0.x, b0.y, b0.z, b0.w, b1.x, b1.y, b1.z, b1.w};
#pragma unroll
            for (int r = 0; r < 8; r++)
#pragma unroll
                for (int c = 0; c < 8; c++) acc[r][c] += ar[r] * br[c];
        }
    }

    float bl[8];
#pragma unroll
    for (int c = 0; c < 8; c++) bl[c] = bias[bn + tx * 8 + c];
#pragma unroll
    for (int r = 0; r < 8; r++) {
        const int row = bm + ty * 8 + r;
        float o[8];
#pragma unroll
        for (int c = 0; c < 8; c++)
            o[c] = __uint_as_float(f2tf((acc[r][c] + bl[c]) * scale));
        *(float4*)&C[row * HD + bn + tx * 8]     = make_float4(o[0], o[1], o[2], o[3]);
        *(float4*)&C[row * HD + bn + tx * 8 + 4] = make_float4(o[4], o[5], o[6], o[7]);
    }
}

// ---------------------------------------------------------------------------
// Attention via mma.sync m16n8k8 tf32.
// CTA = 128 queries x 1 head. 4 warps x 32 rows (2 m-tiles each).
// One-pass streaming softmax (exp args in (0, 1.1): no running max needed;
// the -0.5 bias is constant across keys and cancels in softmax).
// ---------------------------------------------------------------------------
#define KP 72   // k_s / v_s pitch (words): B-frag banks = 8*t4 + g, conflict-free
#define PP 68   // p_s pitch (words): A-frag banks = 4*g + t4, conflict-free
#define ATT_SMEM ((2 * 64 * KP + 128 * PP) * 4)   // 71680 B

__global__ __launch_bounds__(128) void attn_mma(const float* __restrict__ adj) {
    extern __shared__ float sm[];
    float*    k_s  = sm;                 // [d][j]  (transposed), pitch KP
    float*    v_s  = sm + 64 * KP;       // [j][e], pitch KP
    unsigned* p_su = (unsigned*)(sm + 2 * 64 * KP);  // [i][j] tf32 bits, pitch PP

    const int tid  = threadIdx.x;
    const int w    = tid >> 5;
    const int lane = tid & 31;
    const int g    = lane >> 2;       // groupID (row within fragment)
    const int t4   = lane & 3;        // thread-in-group (col within fragment)
    const int qb   = blockIdx.x;      // 0..31 (128 query rows each)
    const int h    = blockIdx.y;      // 0..7
    const int hoff = h * ATT_DIM;
    const int qrow0 = qb * 128 + w * 32;

    // --- q A-fragments, resident in registers for the whole kernel ---------
    unsigned qa[2][8][4];
#pragma unroll
    for (int mi = 0; mi < 2; mi++) {
        const float* r0 = &g_q[(size_t)(qrow0 + mi * 16 + g) * HD + hoff];
        const float* r1 = &g_q[(size_t)(qrow0 + mi * 16 + g + 8) * HD + hoff];
#pragma unroll
        for (int kc = 0; kc < 8; kc++) {
            qa[mi][kc][0] = __float_as_uint(r0[kc * 8 + t4]);
            qa[mi][kc][1] = __float_as_uint(r1[kc * 8 + t4]);
            qa[mi][kc][2] = __float_as_uint(r0[kc * 8 + t4 + 4]);
            qa[mi][kc][3] = __float_as_uint(r1[kc * 8 + t4 + 4]);
        }
    }

    float acc[2][8][4];
#pragma unroll
    for (int mi = 0; mi < 2; mi++)
#pragma unroll
        for (int n = 0; n < 8; n++)
#pragma unroll
            for (int r = 0; r < 4; r++) acc[mi][n][r] = 0.f;
    float rsum[2][2] = {{0.f, 0.f}, {0.f, 0.f}};

    const int sj = tid >> 1;          // 0..63 (staging row)
    const int sd = (tid & 1) * 32;    // 0 / 32 (staging half)

    for (int kb = 0; kb < 64; kb++) {
        // ---- stage k (transposed) and v ----------------------------------
        __syncthreads();   // prior PV reads of k_s/v_s done
        {
            const float* kr = &g_k[(size_t)((kb << 6) + sj) * HD + hoff + sd];
#pragma unroll
            for (int c = 0; c < 8; c++) {
                float4 t = *(const float4*)(kr + c * 4);
                k_s[(sd + c * 4 + 0) * KP + sj] = t.x;
                k_s[(sd + c * 4 + 1) * KP + sj] = t.y;
                k_s[(sd + c * 4 + 2) * KP + sj] = t.z;
                k_s[(sd + c * 4 + 3) * KP + sj] = t.w;
            }
            const float* vr = &g_v[(size_t)((kb << 6) + sj) * HD + hoff + sd];
#pragma unroll
            for (int c = 0; c < 8; c++)
                *(float4*)&v_s[sj * KP + sd + c * 4] = *(const float4*)(vr + c * 4);
        }
        __syncthreads();

        // ---- S = q @ k^T (tensor cores) ----------------------------------
        float sc[2][8][4];
#pragma unroll
        for (int mi = 0; mi < 2; mi++)
#pragma unroll
            for (int n = 0; n < 8; n++)
#pragma unroll
                for (int r = 0; r < 4; r++) sc[mi][n][r] = 0.f;

#pragma unroll
        for (int kc = 0; kc < 8; kc++) {
#pragma unroll
            for (int n = 0; n < 8; n++) {
                unsigned b0 = __float_as_uint(k_s[(kc * 8 + t4) * KP + n * 8 + g]);
                unsigned b1 = __float_as_uint(k_s[(kc * 8 + t4 + 4) * KP + n * 8 + g]);
                mma_tf32(sc[0][n], qa[0][kc], b0, b1);
                mma_tf32(sc[1][n], qa[1][kc], b0, b1);
            }
        }

        // ---- P = exp(sigmoid(S) + 0.1*adj); stage P^T as tf32 ------------
        const size_t abase = (size_t)(qb * 128 + w * 32) * N_NODES + (size_t)kb * 64;
#pragma unroll
        for (int mi = 0; mi < 2; mi++) {
#pragma unroll
            for (int n = 0; n < 8; n++) {
                const int r0 = mi * 16 + g, r1 = r0 + 8;
                const int col = n * 8 + 2 * t4;
                float2 a0 = *(const float2*)&adj[abase + (size_t)r0 * N_NODES + col];
                float2 a1 = *(const float2*)&adj[abase + (size_t)r1 * N_NODES + col];
                float p0 = __expf(__fdividef(1.f, 1.f + __expf(-sc[mi][n][0])) + 0.1f * a0.x);
                float p1 = __expf(__fdividef(1.f, 1.f + __expf(-sc[mi][n][1])) + 0.1f * a0.y);
                float p2 = __expf(__fdividef(1.f, 1.f + __expf(-sc[mi][n][2])) + 0.1f * a1.x);
                float p3 = __expf(__fdividef(1.f, 1.f + __expf(-sc[mi][n][3])) + 0.1f * a1.y);
                unsigned u0 = f2tf(p0), u1 = f2tf(p1), u2 = f2tf(p2), u3 = f2tf(p3);
                rsum[mi][0] += __uint_as_float(u0) + __uint_as_float(u1);
                rsum[mi][1] += __uint_as_float(u2) + __uint_as_float(u3);
                *(uint2*)&p_su[(w * 32 + r0) * PP + col] = make_uint2(u0, u1);
                *(uint2*)&p_su[(w * 32 + r1) * PP + col] = make_uint2(u2, u3);
            }
        }
        __syncwarp();   // p region is warp-private

        // ---- acc += P @ V (tensor cores) ---------------------------------
#pragma unroll
        for (int kc = 0; kc < 8; kc++) {
            unsigned pa[2][4];
#pragma unroll
            for (int mi = 0; mi < 2; mi++) {
                const int r = w * 32 + mi * 16 + g;
                pa[mi][0] = p_su[r * PP + kc * 8 + t4];
                pa[mi][1] = p_su[(r + 8) * PP + kc * 8 + t4];
                pa[mi][2] = p_su[r * PP + kc * 8 + t4 + 4];
                pa[mi][3] = p_su[(r + 8) * PP + kc * 8 + t4 + 4];
            }
#pragma unroll
            for (int n = 0; n < 8; n++) {
                unsigned b0 = __float_as_uint(v_s[(kc * 8 + t4) * KP + n * 8 + g]);
                unsigned b1 = __float_as_uint(v_s[(kc * 8 + t4 + 4) * KP + n * 8 + g]);
                mma_tf32(acc[0][n], pa[0], b0, b1);
                mma_tf32(acc[1][n], pa[1], b0, b1);
            }
        }
    }

    // ---- normalize and write out -----------------------------------------
    float inv[2][2];
#pragma unroll
    for (int mi = 0; mi < 2; mi++)
#pragma unroll
        for (int r = 0; r < 2; r++) {
            float s = rsum[mi][r];
            s += __shfl_xor_sync(0xffffffffu, s, 1);
            s += __shfl_xor_sync(0xffffffffu, s, 2);
            inv[mi][r] = __fdividef(1.f, s);
        }

#pragma unroll
    for (int mi = 0; mi < 2; mi++) {
        const int r0 = qrow0 + mi * 16 + g;
#pragma unroll
        for (int n = 0; n < 8; n++) {
            const int col = hoff + n * 8 + 2 * t4;
            *(float2*)&g_att[(size_t)r0 * HD + col] =
                make_float2(acc[mi][n][0] * inv[mi][0], acc[mi][n][1] * inv[mi][0]);
            *(float2*)&g_att[(size_t)(r0 + 8) * HD + col] =
                make_float2(acc[mi][n][2] * inv[mi][1], acc[mi][n][3] * inv[mi][1]);
        }
    }
}

// ---------------------------------------------------------------------------
// Output projection: out[4096,64] = g_att[4096,512] @ WO[512,64] + bO (fp32)
// ---------------------------------------------------------------------------
__global__ __launch_bounds__(256) void out_gemm(const float* __restrict__ WO,
                                                const float* __restrict__ bO,
                                                float* __restrict__ out) {
    __shared__ float As[32][68];
    __shared__ float Bs[32][68];
    const int tid = threadIdx.x;
    const int tx = tid & 15, ty = tid >> 4;
    const int bm = blockIdx.x * 64;

    float acc[4][4];
#pragma unroll
    for (int a = 0; a < 4; a++)
#pragma unroll
        for (int b = 0; b < 4; b++) acc[a][b] = 0.f;

    const int ar  = tid >> 2;
    const int akg = (tid & 3) * 8;
    const int bk  = tid >> 3;
    const int bjg = (tid & 7) * 8;

    for (int k0 = 0; k0 < HD; k0 += 32) {
        __syncthreads();
#pragma unroll
        for (int c = 0; c < 2; c++) {
            float4 v4 = *(const float4*)&g_att[(size_t)(bm + ar) * HD + k0 + akg + c * 4];
            As[akg + c * 4 + 0][ar] = v4.x;
            As[akg + c * 4 + 1][ar] = v4.y;
            As[akg + c * 4 + 2][ar] = v4.z;
            As[akg + c * 4 + 3][ar] = v4.w;
        }
#pragma unroll
        for (int c = 0; c < 2; c++)
            *(float4*)&Bs[bk][bjg + c * 4] =
                *(const float4*)&WO[(k0 + bk) * 64 + bjg + c * 4];
        __syncthreads();
#pragma unroll
        for (int kk = 0; kk < 32; kk++) {
            float4 a4 = *(float4*)&As[kk][ty * 4];
            float4 b4 = *(float4*)&Bs[kk][tx * 4];
            float arr[4] = {a4.x, a4.y, a4.z, a4.w};
            float brr[4] = {b4.x, b4.y, b4.z, b4.w};
#pragma unroll
            for (int a = 0; a < 4; a++)
#pragma unroll
                for (int b = 0; b < 4; b++) acc[a][b] += arr[a] * brr[b];
        }
    }

    float bl[4];
#pragma unroll
    for (int b = 0; b < 4; b++) bl[b] = bO[tx * 4 + b];
#pragma unroll
    for (int a = 0; a < 4; a++) {
        float4 o;
        o.x = acc[a][0] + bl[0];
        o.y = acc[a][1] + bl[1];
        o.z = acc[a][2] + bl[2];
        o.w = acc[a][3] + bl[3];
        *(float4*)&out[(size_t)(bm + ty * 4 + a) * 64 + tx * 4] = o;
    }
}

// ---------------------------------------------------------------------------
extern "C" void kernel_launch(void* const* d_in, const int* in_sizes, int n_in,
                              void* d_out, int out_size) {
    const float* Q   = (const float*)d_in[0];
    const float* K   = (const float*)d_in[1];
    const float* V   = (const float*)d_in[2];
    const float* adj = (const float*)d_in[3];
    const float* WQ  = (const float*)d_in[4];
    const float* bQ  = (const float*)d_in[5];
    const float* WK  = (const float*)d_in[6];
    const float* bK  = (const float*)d_in[7];
    const float* WV  = (const float*)d_in[8];
    const float* bV  = (const float*)d_in[9];
    const float* WO  = (const float*)d_in[10];
    const float* bO  = (const float*)d_in[11];
    float* out = (float*)d_out;

    float *qp, *kp, *vp;
    cudaGetSymbolAddress((void**)&qp, g_q);
    cudaGetSymbolAddress((void**)&kp, g_k);
    cudaGetSymbolAddress((void**)&vp, g_v);

    dim3 pgrid(HD / 128, N_NODES / 128);
    proj_gemm<<<pgrid, 256>>>(Q, WQ, bQ, qp, 0.125f);  // q pre-scaled by d^-0.5
    proj_gemm<<<pgrid, 256>>>(K, WK, bK, kp, 1.0f);
    proj_gemm<<<pgrid, 256>>>(V, WV, bV, vp, 1.0f);

    cudaFuncSetAttribute(attn_mma,
                         cudaFuncAttributeMaxDynamicSharedMemorySize, ATT_SMEM);
    attn_mma<<<dim3(32, 8), 128, ATT_SMEM>>>(adj);

    out_gemm<<<N_NODES / 64, 256>>>(WO, bO, out);
}